// round 17
// baseline (speedup 1.0000x reference)
#include <cuda_runtime.h>
#include <cuda_bf16.h>
#include <cuda_fp16.h>
#include <math.h>
#include <stdint.h>

#define N_NODES 8192
#define NFEAT   512
#define NHID    256
#define NLAT    64
#define NCLASS  16
#define ALPHA   0.2f
#define NWORDS  (N_NODES / 32)

// ------------------------------ device scratch ------------------------------
__device__ __align__(16) float g_Wh1 [N_NODES * NHID];
__device__ __align__(16) float g_h   [N_NODES * NHID];
__device__ __align__(16) float g_Whmu[N_NODES * NLAT];
__device__ __align__(16) float g_Whlv[N_NODES * NLAT];
__device__ __align__(16) __half g_T1[NHID * N_NODES];
__device__ __align__(16) __half g_Tm[NLAT * N_NODES];
__device__ __align__(16) __half g_Tv[NLAT * N_NODES];
__device__ __align__(16) uint4 g_Bf1[262144];     // [jblk128][ng16][kt4][lane32]
__device__ __align__(16) uint2 g_Bf23[262144];    // [mat2][jblk128][ng8][kt4][lane32]
__device__ unsigned g_adjb[(size_t)N_NODES * NWORDS];
__device__ float g_s1[N_NODES], g_d1[N_NODES];
__device__ float g_smu[N_NODES], g_dmu[N_NODES];
__device__ float g_slv[N_NODES], g_dlv[N_NODES];
__device__ __align__(16) float g_E1[N_NODES],  g_F1[N_NODES];
__device__ __align__(16) float g_Emu[N_NODES], g_Fmu[N_NODES];
__device__ __align__(16) float g_Elv[N_NODES], g_Flv[N_NODES];
__device__ unsigned g_dmaxu[4];
__device__ float    g_dmaxf[4];

// ------------------------------ helpers -------------------------------------
__device__ __forceinline__ uint32_t smem_u32(const void* p) {
    uint32_t a;
    asm("{ .reg .u64 t; cvta.to.shared.u64 t, %1; cvt.u32.u64 %0, t; }"
        : "=r"(a) : "l"(p));
    return a;
}
__device__ __forceinline__ unsigned fenc(float x) {
    int ix = __float_as_int(x);
    return ix >= 0 ? ((unsigned)ix | 0x80000000u) : ~(unsigned)ix;
}
__device__ __forceinline__ float fdec(unsigned u) {
    int ix = (u & 0x80000000u) ? (int)(u & 0x7FFFFFFFu) : ~(int)u;
    return __int_as_float(ix);
}

__device__ __forceinline__ void mma16816(float* c,
    uint32_t a0, uint32_t a1, uint32_t a2, uint32_t a3,
    uint32_t b0, uint32_t b1)
{
    asm volatile(
        "mma.sync.aligned.m16n8k16.row.col.f32.f16.f16.f32 "
        "{%0,%1,%2,%3}, {%4,%5,%6,%7}, {%8,%9}, {%0,%1,%2,%3};"
        : "+f"(c[0]), "+f"(c[1]), "+f"(c[2]), "+f"(c[3])
        : "r"(a0), "r"(a1), "r"(a2), "r"(a3), "r"(b0), "r"(b1));
}
__device__ __forceinline__ void ldsm_x4(uint32_t& r0, uint32_t& r1,
                                        uint32_t& r2, uint32_t& r3, uint32_t addr)
{
    asm volatile("ldmatrix.sync.aligned.m8n8.x4.shared.b16 {%0,%1,%2,%3}, [%4];"
                 : "=r"(r0), "=r"(r1), "=r"(r2), "=r"(r3) : "r"(addr));
}

// =============================================================================
// gemm_mma (unchanged)
// =============================================================================
static constexpr int GP    = 144;
static constexpr int G_AH  = 0;
static constexpr int G_AL  = 18432;
static constexpr int G_B   = 36864;
static constexpr int GSMEM = 46080;

__global__ __launch_bounds__(256, 1)
void gemm_mma_kernel(const float* __restrict__ A, const float* __restrict__ B,
                     float* __restrict__ C, int M, int N, int K,
                     unsigned* __restrict__ dmaxu, int init_flag)
{
    extern __shared__ __align__(16) char smem[];
    const uint32_t sb = smem_u32(smem);
    const int tid = threadIdx.x, warp = tid >> 5, lane = tid & 31;
    const int g = lane >> 2, tq = lane & 3;
    const int wm = warp >> 1, wn = warp & 1;
    const int m0 = blockIdx.y * 128, n0 = blockIdx.x * 64;

    if (init_flag && blockIdx.x == 0 && blockIdx.y == 0 && tid < 4)
        dmaxu[tid] = 0u;

    const uint32_t a_lane = ((lane & 7) + ((lane >> 3) & 1) * 8) * GP + ((lane >> 4) & 1) * 16;
    const uint32_t b_lane = ((lane & 7) + ((lane >> 4) & 1) * 8) * GP + ((lane >> 3) & 1) * 16;

    float acc[2][4][4];
    #pragma unroll
    for (int a = 0; a < 2; ++a)
        #pragma unroll
        for (int b = 0; b < 4; ++b)
            #pragma unroll
            for (int c = 0; c < 4; ++c) acc[a][b][c] = 0.f;

    for (int k0 = 0; k0 < K; k0 += 64) {
        __syncthreads();
        #pragma unroll
        for (int i = 0; i < 8; ++i) {
            int c = tid + i * 256;
            int row = c >> 4, kq = (c & 15) * 4;
            float4 v = *(const float4*)&A[(size_t)(m0 + row) * K + k0 + kq];
            __half h0 = __float2half_rn(v.x), h1 = __float2half_rn(v.y);
            __half h2 = __float2half_rn(v.z), h3 = __float2half_rn(v.w);
            __half l0 = __float2half_rn(v.x - __half2float(h0));
            __half l1 = __float2half_rn(v.y - __half2float(h1));
            __half l2 = __float2half_rn(v.z - __half2float(h2));
            __half l3 = __float2half_rn(v.w - __half2float(h3));
            __half2 hh01 = __halves2half2(h0, h1), hh23 = __halves2half2(h2, h3);
            __half2 ll01 = __halves2half2(l0, l1), ll23 = __halves2half2(l2, l3);
            uint2 ph, pl;
            ph.x = *(uint32_t*)&hh01; ph.y = *(uint32_t*)&hh23;
            pl.x = *(uint32_t*)&ll01; pl.y = *(uint32_t*)&ll23;
            *(uint2*)(smem + G_AH + row * GP + kq * 2) = ph;
            *(uint2*)(smem + G_AL + row * GP + kq * 2) = pl;
        }
        #pragma unroll
        for (int i = 0; i < 4; ++i) {
            int c = tid + i * 256;
            int kk = c >> 4, nq = (c & 15) * 4;
            float4 v = *(const float4*)&B[(size_t)(k0 + kk) * N + n0 + nq];
            *(__half*)(smem + G_B + (nq + 0) * GP + kk * 2) = __float2half_rn(v.x);
            *(__half*)(smem + G_B + (nq + 1) * GP + kk * 2) = __float2half_rn(v.y);
            *(__half*)(smem + G_B + (nq + 2) * GP + kk * 2) = __float2half_rn(v.z);
            *(__half*)(smem + G_B + (nq + 3) * GP + kk * 2) = __float2half_rn(v.w);
        }
        __syncthreads();

        const uint32_t abase = sb + G_AH + (wm * 32) * GP + a_lane;
        const uint32_t bbase = sb + G_B + (wn * 32) * GP + b_lane;
        #pragma unroll
        for (int kt = 0; kt < 4; ++kt) {
            const int koff = kt * 32;
            uint32_t ah[2][4], al[2][4];
            #pragma unroll
            for (int mi = 0; mi < 2; ++mi) {
                ldsm_x4(ah[mi][0], ah[mi][1], ah[mi][2], ah[mi][3],
                        abase + mi * (16 * GP) + koff);
                ldsm_x4(al[mi][0], al[mi][1], al[mi][2], al[mi][3],
                        abase + (G_AL - G_AH) + mi * (16 * GP) + koff);
            }
            #pragma unroll
            for (int nh = 0; nh < 2; ++nh) {
                uint32_t b0, b1, b2, b3;
                ldsm_x4(b0, b1, b2, b3, bbase + nh * (16 * GP) + koff);
                #pragma unroll
                for (int mi = 0; mi < 2; ++mi) {
                    mma16816(acc[mi][nh * 2 + 0], ah[mi][0], ah[mi][1], ah[mi][2], ah[mi][3], b0, b1);
                    mma16816(acc[mi][nh * 2 + 0], al[mi][0], al[mi][1], al[mi][2], al[mi][3], b0, b1);
                    mma16816(acc[mi][nh * 2 + 1], ah[mi][0], ah[mi][1], ah[mi][2], ah[mi][3], b2, b3);
                    mma16816(acc[mi][nh * 2 + 1], al[mi][0], al[mi][1], al[mi][2], al[mi][3], b2, b3);
                }
            }
        }
    }

    #pragma unroll
    for (int mi = 0; mi < 2; ++mi) {
        int r0 = m0 + wm * 32 + mi * 16 + g;
        #pragma unroll
        for (int ni = 0; ni < 4; ++ni) {
            int col = n0 + wn * 32 + ni * 8 + tq * 2;
            *(float2*)&C[(size_t)r0 * N + col] =
                make_float2(acc[mi][ni][0], acc[mi][ni][1]);
            *(float2*)&C[(size_t)(r0 + 8) * N + col] =
                make_float2(acc[mi][ni][2], acc[mi][ni][3]);
        }
    }
}

// =============================================================================
// sd + tconv fused (unchanged)
// =============================================================================
template <int F>
__global__ __launch_bounds__(256)
void sdtconv_kernel(const float* __restrict__ Wh, const float* __restrict__ a,
                    float* __restrict__ s, float* __restrict__ d,
                    unsigned* __restrict__ dmaxu, __half* __restrict__ T)
{
    if (blockIdx.x < 1024) {
        int warp = (blockIdx.x * 256 + threadIdx.x) >> 5;
        int lane = threadIdx.x & 31;
        const float* row = Wh + (size_t)warp * F;
        float ss = 0.f, dd = 0.f;
        #pragma unroll
        for (int f = lane; f < F; f += 32) {
            float w = row[f];
            ss += w * a[f];
            dd += w * a[F + f];
        }
        #pragma unroll
        for (int o = 16; o; o >>= 1) {
            ss += __shfl_down_sync(0xffffffffu, ss, o);
            dd += __shfl_down_sync(0xffffffffu, dd, o);
        }
        if (lane == 0) {
            s[warp] = ss; d[warp] = dd;
            atomicMax(dmaxu, fenc(dd));
        }
    } else {
        __shared__ float tile[32][33];
        int b = blockIdx.x - 1024;
        int f0 = (b % (F / 32)) * 32;
        int m0 = (b / (F / 32)) * 32;
        int x = threadIdx.x & 31, y = threadIdx.x >> 5;
        #pragma unroll
        for (int yy = 0; yy < 4; ++yy)
            tile[y + yy * 8][x] = Wh[(size_t)(m0 + y + yy * 8) * F + f0 + x];
        __syncthreads();
        #pragma unroll
        for (int yy = 0; yy < 4; ++yy) {
            float v = tile[x][y + yy * 8];
            T[(size_t)(f0 + y + yy * 8) * N_NODES + m0 + x] = __float2half_rn(v);
        }
    }
}

// =============================================================================
// efpack: ef + adjacency pack + attn1 B-fragment gen (unchanged)
// =============================================================================
__global__ __launch_bounds__(256)
void efpack_kernel(const float* __restrict__ d, const unsigned* __restrict__ dmaxu,
                   float* __restrict__ E, float* __restrict__ F,
                   float* __restrict__ dmaxf,
                   const int* __restrict__ adj, unsigned* __restrict__ bits,
                   const __half* __restrict__ T1, uint4* __restrict__ Bf1)
{
    if (blockIdx.x < 32) {
        float dm = fdec(*dmaxu);
        int i = blockIdx.x * 256 + threadIdx.x;
        float v = d[i] - dm;
        E[i] = __expf(v);
        F[i] = __expf(ALPHA * v);
        if (i == 0) *dmaxf = dm;
    } else if (blockIdx.x < 32 + 262144) {
        size_t idx = (size_t)(blockIdx.x - 32) * 256 + threadIdx.x;
        int v = adj[idx] > 0;
        unsigned b = __ballot_sync(0xffffffffu, v);
        if ((threadIdx.x & 31) == 0) bits[idx >> 5] = b;
    } else {
        int w = (blockIdx.x - 32 - 262144) * 8 + (threadIdx.x >> 5);
        int lane = threadIdx.x & 31;
        int jblk = w >> 6, ng = (w >> 2) & 15, kt = w & 3;
        int f0 = ng * 16 + (lane >> 2);
        int jb = jblk * 64 + kt * 16 + (lane & 3) * 2;
        const __half* p = T1 + (size_t)f0 * N_NODES + jb;
        uint32_t b0 = *(const uint32_t*)p;
        uint32_t b1 = *(const uint32_t*)(p + 8);
        uint32_t b2 = *(const uint32_t*)(p + (size_t)8 * N_NODES);
        uint32_t b3 = *(const uint32_t*)(p + (size_t)8 * N_NODES + 8);
        Bf1[(size_t)w * 32 + lane] = make_uint4(b0, b1, b2, b3);
    }
}

__global__ __launch_bounds__(256)
void ef_kernel(const float* __restrict__ d, const unsigned* __restrict__ dmaxu,
               float* __restrict__ E, float* __restrict__ F,
               float* __restrict__ dmaxf,
               const __half* __restrict__ T, uint2* __restrict__ Bf, int mat)
{
    if (blockIdx.x < 32) {
        float dm = fdec(*dmaxu);
        int i = blockIdx.x * 256 + threadIdx.x;
        float v = d[i] - dm;
        E[i] = __expf(v);
        F[i] = __expf(ALPHA * v);
        if (i == 0) *dmaxf = dm;
    } else {
        int w = (blockIdx.x - 32) * 8 + (threadIdx.x >> 5);
        int lane = threadIdx.x & 31;
        int jblk = w >> 5, ng = (w >> 2) & 7, kt = w & 3;
        int f0 = ng * 8 + (lane >> 2);
        int jb = jblk * 64 + kt * 16 + (lane & 3) * 2;
        const __half* p = T + (size_t)f0 * N_NODES + jb;
        uint32_t b0 = *(const uint32_t*)p;
        uint32_t b1 = *(const uint32_t*)(p + 8);
        Bf[(size_t)mat * 131072 + (size_t)w * 32 + lane] = make_uint2(b0, b1);
    }
}

// =============================================================================
// attn1: CTA 16 rows x 256 F, 256 thr, 8 warps (16r x 32c each), grid 512.
// 1 A-ldsm per kt per warp; B fragments from GMEM; 4 CTAs/SM target.
// =============================================================================
static constexpr int PA      = 144;
static constexpr int S1_A    = 0;          // 2 buf x 16x144
static constexpr int S1_ABUF = 2304;
static constexpr int S1_ZT   = 4608;       // 256 floats
static constexpr int S1_ZR   = 5632;       // 16 floats
static constexpr int SMEM1   = 5760;

__global__ __launch_bounds__(256, 4)
void attn1_kernel(const unsigned* __restrict__ adjb,
                  const uint4* __restrict__ Bf,
                  const float* __restrict__ svec, const float* __restrict__ dvec,
                  const float* __restrict__ EJ, const float* __restrict__ FJ,
                  const float* __restrict__ dmaxp, float* __restrict__ outp)
{
    extern __shared__ __align__(16) char smem[];
    const uint32_t sb = smem_u32(smem);
    const int tid = threadIdx.x, warp = tid >> 5, lane = tid & 31;
    const int g = lane >> 2, tq = lane & 3;
    const int i0 = blockIdx.x * 16;
    const int n0w = warp * 32;

    const uint32_t a_lane = ((lane & 7) + ((lane >> 3) & 1) * 8) * PA + ((lane >> 4) & 1) * 16;

    const int r = tid >> 4, q = tid & 15;    // row (16), 4-j slice
    const float sv = svec[i0 + r];
    const float mv = sv + *dmaxp;
    const float m_r = mv > 0.f ? mv : ALPHA * mv;
    const float RA = __expf(mv - m_r);
    const float RB = __expf(ALPHA * mv - m_r);
    float zacc = 0.f;

    float acc[4][4];
    #pragma unroll
    for (int b = 0; b < 4; ++b)
        #pragma unroll
        for (int c = 0; c < 4; ++c) acc[b][c] = 0.f;

    const size_t row_adj = (size_t)(i0 + r) * NWORDS;
    const uint4* bfp = Bf + (size_t)warp * 256 + lane;   // + t*2048 (+128 for 2nd ng)

    // ---- prologue: P-gen tile 0 ----------------------------------------------
    {
        unsigned w = adjb[row_adj + (q >> 3)];
        unsigned bits = (w >> ((q & 7) * 4)) & 0xF;
        const int jb = q * 4;
        float4 dd = *(const float4*)(dvec + jb);
        float4 ee = *(const float4*)(EJ + jb);
        float4 ff = *(const float4*)(FJ + jb);
        float p0 = (bits & 1) ? ((sv + dd.x > 0.f) ? RA * ee.x : RB * ff.x) : 0.f;
        float p1 = (bits & 2) ? ((sv + dd.y > 0.f) ? RA * ee.y : RB * ff.y) : 0.f;
        float p2 = (bits & 4) ? ((sv + dd.z > 0.f) ? RA * ee.z : RB * ff.z) : 0.f;
        float p3 = (bits & 8) ? ((sv + dd.w > 0.f) ? RA * ee.w : RB * ff.w) : 0.f;
        zacc += p0 + p1 + p2 + p3;
        __half2 h01 = __floats2half2_rn(p0, p1);
        __half2 h23 = __floats2half2_rn(p2, p3);
        uint2 pk;
        pk.x = *(uint32_t*)&h01; pk.y = *(uint32_t*)&h23;
        *(uint2*)(smem + S1_A + r * PA + jb * 2) = pk;
    }
    __syncthreads();

    for (int t = 0; t < N_NODES / 64; ++t) {
        const int buf = t & 1;

        const uint32_t abase = sb + S1_A + buf * S1_ABUF + a_lane;
        const uint4* bft = bfp + (size_t)t * 2048;
        #pragma unroll
        for (int kt = 0; kt < 4; ++kt) {
            uint4 b0v = bft[kt * 32];
            uint4 b1v = bft[128 + kt * 32];
            uint32_t a0[4];
            ldsm_x4(a0[0], a0[1], a0[2], a0[3], abase + kt * 32);
            mma16816(acc[0], a0[0], a0[1], a0[2], a0[3], b0v.x, b0v.y);
            mma16816(acc[1], a0[0], a0[1], a0[2], a0[3], b0v.z, b0v.w);
            mma16816(acc[2], a0[0], a0[1], a0[2], a0[3], b1v.x, b1v.y);
            mma16816(acc[3], a0[0], a0[1], a0[2], a0[3], b1v.z, b1v.w);
        }

        if (t + 1 < N_NODES / 64) {
            const int j0 = (t + 1) * 64;
            unsigned w = adjb[row_adj + (j0 >> 5) + (q >> 3)];
            unsigned bits = (w >> ((q & 7) * 4)) & 0xF;
            const int jb = q * 4;
            float4 dd = *(const float4*)(dvec + j0 + jb);
            float4 ee = *(const float4*)(EJ + j0 + jb);
            float4 ff = *(const float4*)(FJ + j0 + jb);
            float p0 = (bits & 1) ? ((sv + dd.x > 0.f) ? RA * ee.x : RB * ff.x) : 0.f;
            float p1 = (bits & 2) ? ((sv + dd.y > 0.f) ? RA * ee.y : RB * ff.y) : 0.f;
            float p2 = (bits & 4) ? ((sv + dd.z > 0.f) ? RA * ee.z : RB * ff.z) : 0.f;
            float p3 = (bits & 8) ? ((sv + dd.w > 0.f) ? RA * ee.w : RB * ff.w) : 0.f;
            zacc += p0 + p1 + p2 + p3;
            __half2 h01 = __floats2half2_rn(p0, p1);
            __half2 h23 = __floats2half2_rn(p2, p3);
            uint2 pk;
            pk.x = *(uint32_t*)&h01; pk.y = *(uint32_t*)&h23;
            *(uint2*)(smem + S1_A + (buf ^ 1) * S1_ABUF + r * PA + jb * 2) = pk;
        }
        __syncthreads();
    }

    // ---- epilogue ------------------------------------------------------------
    float* zt = (float*)(smem + S1_ZT);
    float* zr = (float*)(smem + S1_ZR);
    zt[tid] = zacc;
    __syncthreads();
    if (tid < 16) {
        float z = 0.f;
        #pragma unroll
        for (int k = 0; k < 16; ++k) z += zt[16 * tid + k];
        zr[tid] = z;
    }
    __syncthreads();
    {
        float iz0 = 1.f / zr[g];
        float iz1 = 1.f / zr[g + 8];
        #pragma unroll
        for (int ni = 0; ni < 4; ++ni) {
            int col = n0w + ni * 8 + tq * 2;
            float v0 = acc[ni][0] * iz0; v0 = v0 > 0.f ? v0 : expm1f(v0);
            float v1 = acc[ni][1] * iz0; v1 = v1 > 0.f ? v1 : expm1f(v1);
            float v2 = acc[ni][2] * iz1; v2 = v2 > 0.f ? v2 : expm1f(v2);
            float v3 = acc[ni][3] * iz1; v3 = v3 > 0.f ? v3 : expm1f(v3);
            *(float2*)&outp[(size_t)(i0 + g) * NHID + col]     = make_float2(v0, v1);
            *(float2*)&outp[(size_t)(i0 + g + 8) * NHID + col] = make_float2(v2, v3);
        }
    }
}

// =============================================================================
// attn23: CTA 16 rows, 256 thr, 8 warps: which=w>>2, ng=(w&3) (16 cols each).
// warp = 16r x 16n. grid 512. B fragments from GMEM.
// =============================================================================
static constexpr int S2_A    = 0;          // 2 buf x [mu 16x144 | lv 16x144]
static constexpr int S2_ABUF = 4608;
static constexpr int S2_AMAT = 2304;
static constexpr int S2_ZT   = 9216;       // 2 x 256 floats
static constexpr int S2_ZR   = 11264;      // 2 x 16 floats
static constexpr int SMEM2   = 11392;

__global__ __launch_bounds__(256, 4)
void attn23_kernel(const unsigned* __restrict__ adjb,
                   const uint2* __restrict__ Bf,
                   const float* __restrict__ smuv, const float* __restrict__ dmuv,
                   const float* __restrict__ slvv, const float* __restrict__ dlvv,
                   const float* __restrict__ Em, const float* __restrict__ Fm,
                   const float* __restrict__ Ev, const float* __restrict__ Fv,
                   const float* __restrict__ dmaxp,
                   float* __restrict__ out_mu, float* __restrict__ out_lv)
{
    extern __shared__ __align__(16) char smem[];
    const uint32_t sb = smem_u32(smem);
    const int tid = threadIdx.x, warp = tid >> 5, lane = tid & 31;
    const int g = lane >> 2, tq = lane & 3;
    const int i0 = blockIdx.x * 16;
    const int which = warp >> 2;
    const int n0w = (warp & 3) * 16;

    const uint32_t a_lane = ((lane & 7) + ((lane >> 3) & 1) * 8) * PA + ((lane >> 4) & 1) * 16;

    const int r = tid >> 4, q = tid & 15;    // row (16), 4-j slice
    const float svm = smuv[i0 + r], svv = slvv[i0 + r];
    const float mvm = svm + dmaxp[0], mvv = svv + dmaxp[1];
    const float mm = mvm > 0.f ? mvm : ALPHA * mvm;
    const float ml = mvv > 0.f ? mvv : ALPHA * mvv;
    const float RAm = __expf(mvm - mm), RBm = __expf(ALPHA * mvm - mm);
    const float RAv = __expf(mvv - ml), RBv = __expf(ALPHA * mvv - ml);
    float zm = 0.f, zv = 0.f;

    float acc[2][4];
    #pragma unroll
    for (int b = 0; b < 2; ++b)
        #pragma unroll
        for (int c = 0; c < 4; ++c) acc[b][c] = 0.f;

    const size_t row_adj = (size_t)(i0 + r) * NWORDS;
    const uint2* bfp = Bf + (size_t)which * 131072 + (size_t)(warp & 3) * 256 + lane;

    // ---- prologue: P-gen tile 0 (both mats) ----------------------------------
    {
        unsigned w = adjb[row_adj + (q >> 3)];
        unsigned bits = (w >> ((q & 7) * 4)) & 0xF;
        const int jb = q * 4;

        float4 dd = *(const float4*)(dmuv + jb);
        float4 ee = *(const float4*)(Em + jb);
        float4 ff = *(const float4*)(Fm + jb);
        float p0 = (bits & 1) ? ((svm + dd.x > 0.f) ? RAm * ee.x : RBm * ff.x) : 0.f;
        float p1 = (bits & 2) ? ((svm + dd.y > 0.f) ? RAm * ee.y : RBm * ff.y) : 0.f;
        float p2 = (bits & 4) ? ((svm + dd.z > 0.f) ? RAm * ee.z : RBm * ff.z) : 0.f;
        float p3 = (bits & 8) ? ((svm + dd.w > 0.f) ? RAm * ee.w : RBm * ff.w) : 0.f;
        zm += p0 + p1 + p2 + p3;
        __half2 h01 = __floats2half2_rn(p0, p1);
        __half2 h23 = __floats2half2_rn(p2, p3);
        uint2 pk;
        pk.x = *(uint32_t*)&h01; pk.y = *(uint32_t*)&h23;
        *(uint2*)(smem + S2_A + r * PA + jb * 2) = pk;

        dd = *(const float4*)(dlvv + jb);
        ee = *(const float4*)(Ev + jb);
        ff = *(const float4*)(Fv + jb);
        p0 = (bits & 1) ? ((svv + dd.x > 0.f) ? RAv * ee.x : RBv * ff.x) : 0.f;
        p1 = (bits & 2) ? ((svv + dd.y > 0.f) ? RAv * ee.y : RBv * ff.y) : 0.f;
        p2 = (bits & 4) ? ((svv + dd.z > 0.f) ? RAv * ee.z : RBv * ff.z) : 0.f;
        p3 = (bits & 8) ? ((svv + dd.w > 0.f) ? RAv * ee.w : RBv * ff.w) : 0.f;
        zv += p0 + p1 + p2 + p3;
        h01 = __floats2half2_rn(p0, p1);
        h23 = __floats2half2_rn(p2, p3);
        pk.x = *(uint32_t*)&h01; pk.y = *(uint32_t*)&h23;
        *(uint2*)(smem + S2_A + S2_AMAT + r * PA + jb * 2) = pk;
    }
    __syncthreads();

    for (int t = 0; t < N_NODES / 64; ++t) {
        const int buf = t & 1;

        const uint32_t abase = sb + S2_A + buf * S2_ABUF + which * S2_AMAT + a_lane;
        const uint2* bft = bfp + (size_t)t * 1024;
        #pragma unroll
        for (int kt = 0; kt < 4; ++kt) {
            uint2 b0v = bft[kt * 32];
            uint2 b1v = bft[128 + kt * 32];
            uint32_t a0[4];
            ldsm_x4(a0[0], a0[1], a0[2], a0[3], abase + kt * 32);
            mma16816(acc[0], a0[0], a0[1], a0[2], a0[3], b0v.x, b0v.y);
            mma16816(acc[1], a0[0], a0[1], a0[2], a0[3], b1v.x, b1v.y);
        }

        if (t + 1 < N_NODES / 64) {
            const int j0 = (t + 1) * 64;
            unsigned w = adjb[row_adj + (j0 >> 5) + (q >> 3)];
            unsigned bits = (w >> ((q & 7) * 4)) & 0xF;
            const int jb = q * 4;

            float4 dd = *(const float4*)(dmuv + j0 + jb);
            float4 ee = *(const float4*)(Em + j0 + jb);
            float4 ff = *(const float4*)(Fm + j0 + jb);
            float p0 = (bits & 1) ? ((svm + dd.x > 0.f) ? RAm * ee.x : RBm * ff.x) : 0.f;
            float p1 = (bits & 2) ? ((svm + dd.y > 0.f) ? RAm * ee.y : RBm * ff.y) : 0.f;
            float p2 = (bits & 4) ? ((svm + dd.z > 0.f) ? RAm * ee.z : RBm * ff.z) : 0.f;
            float p3 = (bits & 8) ? ((svm + dd.w > 0.f) ? RAm * ee.w : RBm * ff.w) : 0.f;
            zm += p0 + p1 + p2 + p3;
            __half2 h01 = __floats2half2_rn(p0, p1);
            __half2 h23 = __floats2half2_rn(p2, p3);
            uint2 pk;
            pk.x = *(uint32_t*)&h01; pk.y = *(uint32_t*)&h23;
            *(uint2*)(smem + S2_A + (buf ^ 1) * S2_ABUF + r * PA + jb * 2) = pk;

            dd = *(const float4*)(dlvv + j0 + jb);
            ee = *(const float4*)(Ev + j0 + jb);
            ff = *(const float4*)(Fv + j0 + jb);
            p0 = (bits & 1) ? ((svv + dd.x > 0.f) ? RAv * ee.x : RBv * ff.x) : 0.f;
            p1 = (bits & 2) ? ((svv + dd.y > 0.f) ? RAv * ee.y : RBv * ff.y) : 0.f;
            p2 = (bits & 4) ? ((svv + dd.z > 0.f) ? RAv * ee.z : RBv * ff.z) : 0.f;
            p3 = (bits & 8) ? ((svv + dd.w > 0.f) ? RAv * ee.w : RBv * ff.w) : 0.f;
            zv += p0 + p1 + p2 + p3;
            h01 = __floats2half2_rn(p0, p1);
            h23 = __floats2half2_rn(p2, p3);
            pk.x = *(uint32_t*)&h01; pk.y = *(uint32_t*)&h23;
            *(uint2*)(smem + S2_A + (buf ^ 1) * S2_ABUF + S2_AMAT + r * PA + jb * 2) = pk;
        }
        __syncthreads();
    }

    // epilogue
    float* ztm = (float*)(smem + S2_ZT);
    float* ztv = ztm + 256;
    float* zrm = (float*)(smem + S2_ZR);
    float* zrv = zrm + 16;
    ztm[tid] = zm; ztv[tid] = zv;
    __syncthreads();
    if (tid < 16) {
        float a = 0.f, b = 0.f;
        #pragma unroll
        for (int k = 0; k < 16; ++k) { a += ztm[16 * tid + k]; b += ztv[16 * tid + k]; }
        zrm[tid] = a; zrv[tid] = b;
    }
    __syncthreads();
    const float* zrow = which ? zrv : zrm;
    float* outw = which ? out_lv : out_mu;
    {
        float iz0 = 1.f / zrow[g];
        float iz1 = 1.f / zrow[g + 8];
        #pragma unroll
        for (int ni = 0; ni < 2; ++ni) {
            int col = n0w + ni * 8 + tq * 2;
            *(float2*)&outw[(size_t)(i0 + g) * NLAT + col] =
                make_float2(acc[ni][0] * iz0, acc[ni][1] * iz0);
            *(float2*)&outw[(size_t)(i0 + g + 8) * NLAT + col] =
                make_float2(acc[ni][2] * iz1, acc[ni][3] * iz1);
        }
    }
}

// ---------------- z = mu + eps*exp(0.5*lv); logits = z @ Wc + bc ------------
__global__ __launch_bounds__(128)
void final_kernel(const float* __restrict__ mu, const float* __restrict__ lv,
                  const float* __restrict__ eps, const float* __restrict__ Wc,
                  const float* __restrict__ bc, float* __restrict__ logits)
{
    __shared__ float zs[8 * 64];
    const int tid = threadIdx.x;
    const int r0 = blockIdx.x * 8;
    #pragma unroll
    for (int l = tid; l < 8 * 64; l += 128) {
        int r = l >> 6, k = l & 63;
        size_t idx = (size_t)(r0 + r) * 64 + k;
        zs[l] = mu[idx] + eps[idx] * __expf(0.5f * lv[idx]);
    }
    __syncthreads();
    int r = tid >> 4, n = tid & 15;
    float acc = bc[n];
    #pragma unroll
    for (int k = 0; k < 64; ++k) acc += zs[r * 64 + k] * Wc[k * 16 + n];
    logits[(size_t)(r0 + r) * 16 + n] = acc;
}

// ------------------------------ launch --------------------------------------
extern "C" void kernel_launch(void* const* d_in, const int* in_sizes, int n_in,
                              void* d_out, int out_size)
{
    const float* x   = (const float*)d_in[0];
    const int*   adj = (const int*)  d_in[1];
    const float* eps = (const float*)d_in[2];
    const float* W1  = (const float*)d_in[3];
    const float* a1  = (const float*)d_in[4];
    const float* Wmu = (const float*)d_in[5];
    const float* amu = (const float*)d_in[6];
    const float* Wlv = (const float*)d_in[7];
    const float* alv = (const float*)d_in[8];
    const float* Wc  = (const float*)d_in[9];
    const float* bc  = (const float*)d_in[10];

    float* out    = (float*)d_out;
    float* logits = out;
    float* mu     = out + (size_t)N_NODES * NCLASS;
    float* lv     = mu  + (size_t)N_NODES * NLAT;

    float *Wh1, *h, *Whmu, *Whlv, *s1, *d1, *smu, *dmu, *slv, *dlv;
    float *E1, *F1, *Emu, *Fmu, *Elv, *Flv, *dmaxf;
    unsigned *dmaxu;
    __half *T1, *Tm, *Tv;
    uint4 *Bf1;
    uint2 *Bf23;
    unsigned* adjb;
    cudaGetSymbolAddress((void**)&Wh1,  g_Wh1);
    cudaGetSymbolAddress((void**)&h,    g_h);
    cudaGetSymbolAddress((void**)&Whmu, g_Whmu);
    cudaGetSymbolAddress((void**)&Whlv, g_Whlv);
    cudaGetSymbolAddress((void**)&s1,   g_s1);
    cudaGetSymbolAddress((void**)&d1,   g_d1);
    cudaGetSymbolAddress((void**)&smu,  g_smu);
    cudaGetSymbolAddress((void**)&dmu,  g_dmu);
    cudaGetSymbolAddress((void**)&slv,  g_slv);
    cudaGetSymbolAddress((void**)&dlv,  g_dlv);
    cudaGetSymbolAddress((void**)&dmaxu, g_dmaxu);
    cudaGetSymbolAddress((void**)&dmaxf, g_dmaxf);
    cudaGetSymbolAddress((void**)&E1,   g_E1);
    cudaGetSymbolAddress((void**)&F1,   g_F1);
    cudaGetSymbolAddress((void**)&Emu,  g_Emu);
    cudaGetSymbolAddress((void**)&Fmu,  g_Fmu);
    cudaGetSymbolAddress((void**)&Elv,  g_Elv);
    cudaGetSymbolAddress((void**)&Flv,  g_Flv);
    cudaGetSymbolAddress((void**)&T1,   g_T1);
    cudaGetSymbolAddress((void**)&Tm,   g_Tm);
    cudaGetSymbolAddress((void**)&Tv,   g_Tv);
    cudaGetSymbolAddress((void**)&Bf1,  g_Bf1);
    cudaGetSymbolAddress((void**)&Bf23, g_Bf23);
    cudaGetSymbolAddress((void**)&adjb, g_adjb);

    cudaFuncSetAttribute(gemm_mma_kernel, cudaFuncAttributeMaxDynamicSharedMemorySize, GSMEM);
    cudaFuncSetAttribute(attn1_kernel,  cudaFuncAttributeMaxDynamicSharedMemorySize, SMEM1);
    cudaFuncSetAttribute(attn23_kernel, cudaFuncAttributeMaxDynamicSharedMemorySize, SMEM2);

    // 0: gemm1 (inits dmax)
    gemm_mma_kernel<<<dim3(NHID / 64, N_NODES / 128), 256, GSMEM>>>(
        x, W1, Wh1, N_NODES, NHID, NFEAT, dmaxu, 1);
    // 1: sd + tconv
    sdtconv_kernel<NHID><<<1024 + (NHID / 32) * (N_NODES / 32), 256>>>(
        Wh1, a1, s1, d1, dmaxu + 0, T1);
    // 2: ef + pack_adj + attn1 B-fragment gen
    efpack_kernel<<<32 + 262144 + 1024, 256>>>(
        d1, dmaxu + 0, E1, F1, dmaxf + 0, adj, adjb, T1, Bf1);
    // 3: attn1 (profile slot)
    attn1_kernel<<<N_NODES / 16, 256, SMEM1>>>(adjb, Bf1, s1, d1, E1, F1, dmaxf + 0, h);

    // layer 2/3
    gemm_mma_kernel<<<dim3(NLAT / 64, N_NODES / 128), 256, GSMEM>>>(
        h, Wmu, Whmu, N_NODES, NLAT, NHID, dmaxu, 0);
    gemm_mma_kernel<<<dim3(NLAT / 64, N_NODES / 128), 256, GSMEM>>>(
        h, Wlv, Whlv, N_NODES, NLAT, NHID, dmaxu, 0);
    sdtconv_kernel<NLAT><<<1024 + (NLAT / 32) * (N_NODES / 32), 256>>>(
        Whmu, amu, smu, dmu, dmaxu + 1, Tm);
    sdtconv_kernel<NLAT><<<1024 + (NLAT / 32) * (N_NODES / 32), 256>>>(
        Whlv, alv, slv, dlv, dmaxu + 2, Tv);
    ef_kernel<<<32 + 512, 256>>>(dmu, dmaxu + 1, Emu, Fmu, dmaxf + 1, Tm, Bf23, 0);
    ef_kernel<<<32 + 512, 256>>>(dlv, dmaxu + 2, Elv, Flv, dmaxf + 2, Tv, Bf23, 1);
    attn23_kernel<<<N_NODES / 16, 256, SMEM2>>>(adjb, Bf23,
                                                smu, dmu, slv, dlv,
                                                Emu, Fmu, Elv, Flv, dmaxf + 1, mu, lv);

    // reparameterize + classifier
    final_kernel<<<N_NODES / 8, 128>>>(mu, lv, eps, Wc, bc, logits);
}